// round 3
// baseline (speedup 1.0000x reference)
#include <cuda_runtime.h>
#include <math.h>

// Problem dims
#define BB 8
#define TT 250
#define SS 64
#define NSAMP 64000
#define NREG 251          // head(128) + 249 full segments(256) + tail(128)

// Scratch (no cudaMalloc allowed)
__device__ float  g_freqf[BB*TT*SS];
__device__ float  g_amp  [BB*TT*SS];
__device__ float4 g_p4   [BB*NREG*SS];   // {w = omega_j, q = dOmega/512, a0, da}
__device__ float  g_pb   [BB*NREG*SS];   // segment base phase, reduced mod 2pi

// ---------------------------------------------------------------------------
// Stage A: control-rate elementwise math (128k elems).
// Replicates the reference's fp32 rounding points for frequency, since a
// 1-ulp freq error integrates into ~7e-4 rad of phase over 64000 samples.
// ---------------------------------------------------------------------------
__global__ void controls_kernel(const float* __restrict__ amps_in,
                                const float* __restrict__ freqs_in) {
    int idx = blockIdx.x * blockDim.x + threadIdx.x;
    if (idx >= BB*TT*SS) return;

    // frequencies_sigmoid (depth=1):
    //   unit = sigmoid(f)                      (f32 in ref; we round correctly)
    //   midi = MIDI_MAX * unit                 (f32)  [midi_min = 0]
    //   freq = 440 * 2^((midi-69)/12)          (f32 pow)
    double y  = (double)freqs_in[idx];
    double ud = 1.0 / (1.0 + exp(-y));
    float  uf = (float)ud;
    const float MIDI_MAX = 119.21309485364912f;    // np.float32(hz_to_midi(8000))
    float midi = uf * MIDI_MAX;
    float e    = (midi - 69.0f) / 12.0f;
    float pw   = (float)exp2((double)e);           // correctly-rounded 2^e
    float freq = 440.0f * pw;

    // exp_sigmoid(amplitudes) = 2 * sigmoid(x)^log(10) + 1e-7
    double x  = (double)amps_in[idx];
    double sd = 1.0 / (1.0 + exp(-x));
    float  sf = (float)sd;
    float  a  = 2.0f * powf(sf, 2.3025850929940457f) + 1e-7f;

    // remove_above_nyquist (pre-resample; interp endpoints < 8000 => interior too)
    if (freq >= 8000.0f) a = 0.0f;

    g_freqf[idx] = freq;
    g_amp[idx]   = a;
}

// ---------------------------------------------------------------------------
// Stage B: per-(b,s) exact segment-start phases in fp64 (the "cumsum"),
// reduced mod 2pi, plus per-segment linear-phase coefficients.
//
// jax.image.resize 'linear' (upsample x256): coord(i) = (i+0.5)/256 - 0.5.
//   region 0   : samples [0,128)        constant f[0]
//   region r   : samples [256r-128, +256) lerp f[r-1] -> f[r], frac=(2i+1)/512
//   region 250 : samples [63872,64000)  constant f[249]
// Within a region, inclusive cumsum offset for k = i+1 samples:
//   dPhi = k*omega_{r-1} + k^2 * (dOmega/512)
// ---------------------------------------------------------------------------
__global__ void segbase_kernel() {
    int tid = blockIdx.x * blockDim.x + threadIdx.x;
    if (tid >= BB*SS) return;
    int b = tid / SS, s = tid % SS;

    const float  CF     = 3.9269908169872414e-4f;  // fp32(2*pi/16000), as in ref
    const double c      = (double)CF;
    const double TWO_PI = 6.283185307179586476925287;
    const double INV2PI = 0.15915494309189533576888;

    const float* fp = g_freqf + (size_t)b*TT*SS + s;
    const float* ap = g_amp   + (size_t)b*TT*SS + s;

    double om_prev = c * (double)fp[0];
    float  a_prev  = ap[0];

    // region 0 (head): base = 0, phi(i) = (i+1)*omega_0
    int idx0 = (b*NREG + 0)*SS + s;
    g_pb[idx0] = 0.0f;
    g_p4[idx0] = make_float4((float)om_prev, 0.0f, a_prev, 0.0f);

    double P = 128.0 * om_prev;   // phase through sample 127

    for (int r = 1; r <= 249; r++) {
        double om = c * (double)fp[r*SS];
        float  a  = ap[r*SS];
        double n  = rint(P * INV2PI);
        float  base = (float)fma(n, -TWO_PI, P);
        int idx = (b*NREG + r)*SS + s;
        g_pb[idx] = base;
        g_p4[idx] = make_float4((float)om_prev,
                                (float)((om - om_prev) * (1.0/512.0)),
                                a_prev, a - a_prev);
        P += 128.0 * (om_prev + om);   // full 256-sample segment integral
        om_prev = om;
        a_prev  = a;
    }

    // region 250 (tail): constant f[249]
    {
        double n  = rint(P * INV2PI);
        float  base = (float)fma(n, -TWO_PI, P);
        int idx = (b*NREG + 250)*SS + s;
        g_pb[idx] = base;
        g_p4[idx] = make_float4((float)om_prev, 0.0f, a_prev, 0.0f);
    }
}

// ---------------------------------------------------------------------------
// Stage C: audio-rate synthesis. One block = one region of one batch.
// 256 threads (1 sample each) x 64 harmonics.
// Phase in fp32 (offsets <= ~1300 rad, base pre-reduced), fma Cody-Waite
// mod-2pi (error ~1e-7 rad), MUFU __sinf on [-pi,pi].
// ---------------------------------------------------------------------------
__global__ void __launch_bounds__(256) synth_kernel(float* __restrict__ out) {
    __shared__ float4 sp[SS];
    __shared__ float  sb[SS];

    int b = blockIdx.x / NREG;
    int r = blockIdx.x % NREG;
    int tid = threadIdx.x;

    if (tid < SS) {
        int idx = (b*NREG + r)*SS + tid;
        sp[tid] = g_p4[idx];
        sb[tid] = g_pb[idx];
    }
    __syncthreads();

    int n0, len;
    if (r == 0)        { n0 = 0;         len = 128; }
    else if (r == 250) { n0 = 63872;     len = 128; }
    else               { n0 = 256*r-128; len = 256; }
    if (tid >= len) return;

    float kf = (float)(tid + 1);
    float k2 = kf * kf;
    float fr = (float)(2*tid + 1) * (1.0f/512.0f);   // interp frac (2i+1)/512

    const float INV2PI_F = 0.15915494309189535f;
    const float MC1 = -6.28318548202514648f;   // -float(2pi)
    const float MC2 =  1.7484556e-7f;          // float(2pi) - 2pi (hi-lo split)

    float acc = 0.0f;
    #pragma unroll
    for (int s = 0; s < SS; s++) {
        float4 p   = sp[s];
        float base = sb[s];
        float t = fmaf(kf, p.x, base);
        t       = fmaf(k2, p.y, t);
        float nn = rintf(t * INV2PI_F);
        float rr = fmaf(nn, MC1, t);    // t - n*C1   (fma: single rounding)
        rr       = fmaf(nn, MC2, rr);   // += n*(C1-2pi)  =>  t - n*2pi
        float sv = __sinf(rr);
        float am = fmaf(fr, p.w, p.z);
        acc = fmaf(am, sv, acc);
    }
    out[(size_t)b*NSAMP + n0 + tid] = acc;
}

// ---------------------------------------------------------------------------
extern "C" void kernel_launch(void* const* d_in, const int* in_sizes, int n_in,
                              void* d_out, int out_size) {
    const float* amplitudes  = (const float*)d_in[0];
    const float* frequencies = (const float*)d_in[1];
    float* out = (float*)d_out;
    (void)in_sizes; (void)n_in; (void)out_size;

    controls_kernel<<<(BB*TT*SS + 255)/256, 256>>>(amplitudes, frequencies);
    segbase_kernel<<<2, 256>>>();
    synth_kernel<<<BB*NREG, 256>>>(out);
}

// round 4
// speedup vs baseline: 6.0968x; 6.0968x over previous
#include <cuda_runtime.h>
#include <math.h>

// Problem dims
#define BB 8
#define TT 250
#define SS 64
#define NSAMP 64000
#define NREG 251          // head(128) + 249 full segments(256) + tail(128)

// Scratch (no cudaMalloc allowed)
__device__ float4 g_p4[BB*NREG*SS];   // {w = omega_j, q = dOmega/512, a0, da}
__device__ float  g_pb[BB*NREG*SS];   // segment base phase, reduced mod 2pi

// ---------------------------------------------------------------------------
// Fused stage A+B: one block per (b,s) pair.  Thread t computes the control-
// rate math for control point t (freq path in fp64 to preserve the validated
// phase accuracy; amp path in fp32 — amplitude enters the output linearly so
// ~1e-5 rel error is invisible).  Then a block-parallel fp64 Hillis-Steele
// scan produces the segment-start phases that previously came from a serial
// 250-step loop running on only 2 SMs.
//
// jax.image.resize 'linear' (upsample x256): coord(i) = (i+0.5)/256 - 0.5.
//   region 0   : samples [0,128)          constant f[0]
//   region r   : samples [256r-128,+256)  lerp f[r-1]->f[r], frac=(2i+1)/512
//   region 250 : samples [63872,64000)    constant f[249]
// Segment-start phase: base_r = sum_{j<=r} e_j with
//   e_1 = 128*om_0,  e_j = 128*(om_{j-2} + om_{j-1})  (j = 2..250)
// ---------------------------------------------------------------------------
__global__ void __launch_bounds__(256) prep_kernel(const float* __restrict__ amps_in,
                                                   const float* __restrict__ freqs_in) {
    __shared__ double s_om[TT];
    __shared__ float  s_a[TT];
    __shared__ double s_scan[256];

    int b = blockIdx.x / SS;
    int s = blockIdx.x % SS;
    int t = threadIdx.x;

    if (t < TT) {
        int gidx = (b*TT + t)*SS + s;

        // frequencies_sigmoid (depth=1) — fp64 path, identical to the version
        // that passed with margin (1-ulp freq errors integrate to ~7e-4 rad).
        double y  = (double)freqs_in[gidx];
        double ud = 1.0 / (1.0 + exp(-y));
        float  uf = (float)ud;
        const float MIDI_MAX = 119.21309485364912f;   // np.float32(hz_to_midi(8000))
        float midi = uf * MIDI_MAX;
        float e    = (midi - 69.0f) / 12.0f;
        float pw   = (float)exp2((double)e);
        float freq = 440.0f * pw;

        // exp_sigmoid(amplitudes) = 2 * sigmoid(x)^log(10) + 1e-7  (fp32 fast path)
        float x  = amps_in[gidx];
        float sf = 1.0f / (1.0f + __expf(-x));
        float a  = 2.0f * __powf(sf, 2.3025850929940457f) + 1e-7f;

        if (freq >= 8000.0f) a = 0.0f;   // remove_above_nyquist

        const double c = (double)3.9269908169872414e-4f;  // fp32(2*pi/16000)
        s_om[t] = c * (double)freq;
        s_a[t]  = a;
    }
    __syncthreads();

    // Segment increments: thread r holds e_r (r = 1..250), else 0.
    double ev = 0.0;
    if (t == 1)                 ev = 128.0 * s_om[0];
    else if (t >= 2 && t <= 250) ev = 128.0 * (s_om[t-2] + s_om[t-1]);
    s_scan[t] = ev;
    __syncthreads();

    // Inclusive Hillis-Steele scan over 256 entries (8 steps).
    #pragma unroll
    for (int off = 1; off < 256; off <<= 1) {
        double v   = s_scan[t];
        double add = (t >= off) ? s_scan[t - off] : 0.0;
        __syncthreads();
        s_scan[t] = v + add;
        __syncthreads();
    }
    double P = s_scan[t];     // base phase of region t

    if (t <= 250) {
        const double TWO_PI = 6.283185307179586476925287;
        const double INV2PI = 0.15915494309189533576888;
        double n    = rint(P * INV2PI);
        float  base = (float)fma(n, -TWO_PI, P);

        float w, q, a0, da;
        if (t == 0) {
            w = (float)s_om[0];   q = 0.0f; a0 = s_a[0];   da = 0.0f; base = 0.0f;
        } else if (t == 250) {
            w = (float)s_om[249]; q = 0.0f; a0 = s_a[249]; da = 0.0f;
        } else {
            w  = (float)s_om[t-1];
            q  = (float)((s_om[t] - s_om[t-1]) * (1.0/512.0));
            a0 = s_a[t-1];
            da = s_a[t] - s_a[t-1];
        }
        int idx = (b*NREG + t)*SS + s;
        g_pb[idx] = base;
        g_p4[idx] = make_float4(w, q, a0, da);
    }
}

// ---------------------------------------------------------------------------
// Stage C: audio-rate synthesis. One block = one region of one batch.
// 256 threads (1 sample each) x 64 harmonics.
// Phase in fp32 (offsets <= ~1600 rad, base pre-reduced), fma Cody-Waite
// mod-2pi (error ~1e-7 rad), MUFU __sinf on [-pi,pi].
// ---------------------------------------------------------------------------
__global__ void __launch_bounds__(256) synth_kernel(float* __restrict__ out) {
    __shared__ float4 sp[SS];
    __shared__ float  sb[SS];

    int b   = blockIdx.x / NREG;
    int r   = blockIdx.x % NREG;
    int tid = threadIdx.x;

    if (tid < SS) {
        int idx = (b*NREG + r)*SS + tid;
        sp[tid] = g_p4[idx];
        sb[tid] = g_pb[idx];
    }
    __syncthreads();

    int n0, len;
    if (r == 0)        { n0 = 0;         len = 128; }
    else if (r == 250) { n0 = 63872;     len = 128; }
    else               { n0 = 256*r-128; len = 256; }
    if (tid >= len) return;

    float kf = (float)(tid + 1);
    float k2 = kf * kf;
    float fr = (float)(2*tid + 1) * (1.0f/512.0f);   // interp frac (2i+1)/512

    const float INV2PI_F = 0.15915494309189535f;
    const float MC1 = -6.28318548202514648f;   // -float(2pi)
    const float MC2 =  1.7484556e-7f;          // float(2pi) - 2pi (hi-lo split)

    float acc = 0.0f;
    #pragma unroll
    for (int s = 0; s < SS; s++) {
        float4 p   = sp[s];
        float base = sb[s];
        float t = fmaf(kf, p.x, base);
        t       = fmaf(k2, p.y, t);
        float nn = rintf(t * INV2PI_F);
        float rr = fmaf(nn, MC1, t);    // t - n*C1   (fma: single rounding)
        rr       = fmaf(nn, MC2, rr);   // += n*(C1-2pi)  =>  t - n*2pi
        float sv = __sinf(rr);
        float am = fmaf(fr, p.w, p.z);
        acc = fmaf(am, sv, acc);
    }
    out[(size_t)b*NSAMP + n0 + tid] = acc;
}

// ---------------------------------------------------------------------------
extern "C" void kernel_launch(void* const* d_in, const int* in_sizes, int n_in,
                              void* d_out, int out_size) {
    const float* amplitudes  = (const float*)d_in[0];
    const float* frequencies = (const float*)d_in[1];
    float* out = (float*)d_out;
    (void)in_sizes; (void)n_in; (void)out_size;

    prep_kernel<<<BB*SS, 256>>>(amplitudes, frequencies);
    synth_kernel<<<BB*NREG, 256>>>(out);
}

// round 5
// speedup vs baseline: 6.7101x; 1.1006x over previous
#include <cuda_runtime.h>
#include <math.h>

// Problem dims
#define BB 8
#define TT 250
#define SS 64
#define NSAMP 64000
#define NREG 251          // head(128) + 249 full segments(256) + tail(128)

// Scratch (no cudaMalloc allowed)
__device__ float4 g_p4[BB*NREG*SS];   // {w' (midpoint omega), q = dOmega/512, base' (mod 2pi), a0}
__device__ float  g_da[BB*NREG*SS];   // amp delta

// ---------------------------------------------------------------------------
// Fast fp64 exp: rel err ~6e-15 -> rounds to the same f32 as libm exp
// for all practical inputs.  Valid for |x| < ~700.
// ---------------------------------------------------------------------------
__device__ __forceinline__ double fast_exp(double x) {
    const double LOG2E = 1.4426950408889634074;
    const double LN2HI = 6.93147180369123816490e-01;
    const double LN2LO = 1.90821492927058770002e-10;
    double n = rint(x * LOG2E);
    double r = fma(n, -LN2HI, x);
    r        = fma(n, -LN2LO, r);
    double p =        1.0/39916800.0;
    p = fma(p, r, 1.0/3628800.0);
    p = fma(p, r, 1.0/362880.0);
    p = fma(p, r, 1.0/40320.0);
    p = fma(p, r, 1.0/5040.0);
    p = fma(p, r, 1.0/720.0);
    p = fma(p, r, 1.0/120.0);
    p = fma(p, r, 1.0/24.0);
    p = fma(p, r, 1.0/6.0);
    p = fma(p, r, 0.5);
    p = fma(p, r, 1.0);
    p = fma(p, r, 1.0);
    long long ni = (long long)n;
    double sc = __longlong_as_double((unsigned long long)(ni + 1023) << 52);
    return p * sc;
}

// ---------------------------------------------------------------------------
// Packed f32x2 helpers (FFMA2 — only reachable via PTX fma.rn.f32x2)
// ---------------------------------------------------------------------------
__device__ __forceinline__ unsigned long long pk2(float lo, float hi) {
    unsigned long long p;
    asm("mov.b64 %0, {%1, %2};" : "=l"(p) : "f"(lo), "f"(hi));
    return p;
}
__device__ __forceinline__ void upk2(unsigned long long p, float& lo, float& hi) {
    asm("mov.b64 {%0, %1}, %2;" : "=f"(lo), "=f"(hi) : "l"(p));
}
__device__ __forceinline__ unsigned long long fma2(unsigned long long a,
                                                   unsigned long long b,
                                                   unsigned long long c) {
    unsigned long long d;
    asm("fma.rn.f32x2 %0, %1, %2, %3;" : "=l"(d) : "l"(a), "l"(b), "l"(c));
    return d;
}

// ---------------------------------------------------------------------------
// Fused prep: one block per (b,s) pair.  Thread t handles control point t
// (freq path via fp64 fast_exp — preserves the validated phase accuracy),
// then a block-parallel fp64 scan gives exact segment base phases.
//
// jax.image.resize 'linear' (x256): coord(i) = (i+0.5)/256 - 0.5.
//   region 0   : samples [0,128)          constant f[0]
//   region r   : samples [256r-128,+256)  lerp f[r-1]->f[r], frac=(2i+1)/512
//   region 250 : samples [63872,64000)    constant f[249]
// phi(k) = P_base + k*om_prev + k^2*q,  k = 1..len.
// Recentred at kc = len/2:  k' = k-kc,
//   base' = P_base + kc*om_prev + kc^2*q   (reduced mod 2pi in fp64)
//   w'    = om_prev + 2*kc*q               (midpoint omega)
//   phi   = base' + k'*w' + k'^2*q         (|phi| <= ~500 rad)
// ---------------------------------------------------------------------------
__global__ void __launch_bounds__(256) prep_kernel(const float* __restrict__ amps_in,
                                                   const float* __restrict__ freqs_in) {
    __shared__ double s_om[TT];
    __shared__ float  s_a[TT];
    __shared__ double s_scan[256];

    int b = blockIdx.x / SS;
    int s = blockIdx.x % SS;
    int t = threadIdx.x;

    if (t < TT) {
        int gidx = (b*TT + t)*SS + s;

        // frequencies_sigmoid (depth=1), fp64 path (matches passing version)
        double y  = (double)freqs_in[gidx];
        double ud = 1.0 / (1.0 + fast_exp(-y));
        float  uf = (float)ud;
        const float MIDI_MAX = 119.21309485364912f;   // np.float32(hz_to_midi(8000))
        float midi = uf * MIDI_MAX;
        float e    = (midi - 69.0f) / 12.0f;
        float pw   = (float)fast_exp((double)e * 0.6931471805599453);  // 2^e
        float freq = 440.0f * pw;

        // exp_sigmoid(amplitudes): fp32 fast path (amp enters linearly)
        float x  = amps_in[gidx];
        float sf = 1.0f / (1.0f + __expf(-x));
        float a  = 2.0f * __powf(sf, 2.3025850929940457f) + 1e-7f;

        if (freq >= 8000.0f) a = 0.0f;   // remove_above_nyquist

        const double c = (double)3.9269908169872414e-4f;  // fp32(2*pi/16000)
        s_om[t] = c * (double)freq;
        s_a[t]  = a;
    }
    __syncthreads();

    // Segment increments: e_1 = 128*om_0; e_j = 128*(om_{j-2}+om_{j-1}).
    double ev = 0.0;
    if (t == 1)                  ev = 128.0 * s_om[0];
    else if (t >= 2 && t <= 250) ev = 128.0 * (s_om[t-2] + s_om[t-1]);
    s_scan[t] = ev;
    __syncthreads();

    // Inclusive Hillis-Steele scan (8 steps). s_scan[t] -> P_base of region t.
    #pragma unroll
    for (int off = 1; off < 256; off <<= 1) {
        double v   = s_scan[t];
        double add = (t >= off) ? s_scan[t - off] : 0.0;
        __syncthreads();
        s_scan[t] = v + add;
        __syncthreads();
    }

    if (t <= 250) {
        double P = s_scan[t];
        double base_d, w_d, q_d;
        float a0, da;
        if (t == 0) {
            w_d = s_om[0];   q_d = 0.0; base_d = 64.0 * w_d;
            a0 = s_a[0];     da = 0.0f;
        } else if (t == 250) {
            w_d = s_om[249]; q_d = 0.0; base_d = P + 64.0 * w_d;
            a0 = s_a[249];   da = 0.0f;
        } else {
            double om_p = s_om[t-1], om = s_om[t];
            q_d    = (om - om_p) * (1.0/512.0);
            w_d    = 0.5 * (om_p + om);                 // om_p + 256*q
            base_d = P + 96.0*om_p + 32.0*om;           // P + 128*om_p + 16384*q
            a0 = s_a[t-1];   da = s_a[t] - s_a[t-1];
        }
        const double TWO_PI = 6.283185307179586476925287;
        const double INV2PI = 0.15915494309189533576888;
        double n    = rint(base_d * INV2PI);
        float  base = (float)fma(n, -TWO_PI, base_d);

        int idx = (b*NREG + t)*SS + s;
        g_p4[idx] = make_float4((float)w_d, (float)q_d, base, a0);
        g_da[idx] = da;
    }
}

// ---------------------------------------------------------------------------
// Synthesis: one block (128 threads) per region; each thread = 2 samples,
// packed f32x2 math.  64 harmonics; params pre-duplicated in smem so packed
// FFMA2 operands come straight from LDS.128.  sin via __sinf (MUFU) on the
// recentred phase (|t| <= ~500 rad -> jitter ~6e-5 rad, below fp32 floor).
// ---------------------------------------------------------------------------
__global__ void __launch_bounds__(128) synth_kernel(float* __restrict__ out) {
    __shared__ alignas(16) float sp[SS][12];  // [w,w][q,q][b,b][a0,a0][da,da][pad]

    int b   = blockIdx.x / NREG;
    int r   = blockIdx.x % NREG;
    int tid = threadIdx.x;

    if (tid < SS) {
        int idx = (b*NREG + r)*SS + tid;
        float4 v = g_p4[idx];
        float  d = g_da[idx];
        sp[tid][0] = v.x; sp[tid][1] = v.x;
        sp[tid][2] = v.y; sp[tid][3] = v.y;
        sp[tid][4] = v.z; sp[tid][5] = v.z;
        sp[tid][6] = v.w; sp[tid][7] = v.w;
        sp[tid][8] = d;   sp[tid][9] = d;
    }
    __syncthreads();

    int n0, half;
    if (r == 0)        { n0 = 0;         half = 64;  }
    else if (r == 250) { n0 = 63872;     half = 64;  }
    else               { n0 = 256*r-128; half = 128; }
    if (tid >= half) return;

    // samples i0 = tid, i1 = tid+half;  k' = (i+1) - half
    float k0 = (float)(tid + 1 - half);
    float k1 = (float)(tid + 1);
    unsigned long long kp  = pk2(k0, k1);
    unsigned long long fr2 = pk2((float)(2*tid + 1)          * (1.0f/512.0f),
                                 (float)(2*(tid + half) + 1) * (1.0f/512.0f));
    unsigned long long acc = 0ull;   // {0.0f, 0.0f}

    #pragma unroll
    for (int s = 0; s < SS; s++) {
        const unsigned long long* q8 = (const unsigned long long*)sp[s];
        unsigned long long ww = q8[0];
        unsigned long long qq = q8[1];
        unsigned long long bb = q8[2];
        unsigned long long aa = q8[3];
        unsigned long long dd = q8[4];

        unsigned long long h2 = fma2(kp, qq, ww);   // w' + k'q
        unsigned long long t2 = fma2(kp, h2, bb);   // base' + k'(w' + k'q)
        float t0, t1; upk2(t2, t0, t1);
        float s0 = __sinf(t0);
        float s1 = __sinf(t1);
        unsigned long long sv = pk2(s0, s1);
        unsigned long long am = fma2(fr2, dd, aa);  // a0 + fr*da
        acc = fma2(am, sv, acc);
    }

    float o0, o1; upk2(acc, o0, o1);
    out[(size_t)b*NSAMP + n0 + tid]        = o0;
    out[(size_t)b*NSAMP + n0 + tid + half] = o1;
}

// ---------------------------------------------------------------------------
extern "C" void kernel_launch(void* const* d_in, const int* in_sizes, int n_in,
                              void* d_out, int out_size) {
    const float* amplitudes  = (const float*)d_in[0];
    const float* frequencies = (const float*)d_in[1];
    float* out = (float*)d_out;
    (void)in_sizes; (void)n_in; (void)out_size;

    prep_kernel<<<BB*SS, 256>>>(amplitudes, frequencies);
    synth_kernel<<<BB*NREG, 128>>>(out);
}

// round 6
// speedup vs baseline: 12.1191x; 1.8061x over previous
#include <cuda_runtime.h>
#include <math.h>

// Problem dims
#define BB 8
#define TT 250
#define SS 64
#define NSAMP 64000
#define NREG 251          // head(128) + 249 full segments(256) + tail(128)

// Scratch (no cudaMalloc allowed)
__device__ float4 g_p4[BB*NREG*SS];   // {w' (midpoint omega), q, base' (mod 2pi), a0}
__device__ float  g_da[BB*NREG*SS];   // amp delta

// ===========================================================================
// double-single (two-float) arithmetic on the fp32 pipe.  All building blocks
// are exact-FMA based; rel accuracy ~2^-47, latency 4-cyc chains (vs 64-cyc
// fp64 DFMA chains that made prep latency-bound).
// ===========================================================================
struct ff { float h, l; };

__device__ __forceinline__ ff ff_two_prod(float a, float b) {
    float p = a * b;
    float e = fmaf(a, b, -p);
    return {p, e};
}
// full two-float add (Knuth two-sum, branchless)
__device__ __forceinline__ ff ff_add(ff a, ff b) {
    float s  = a.h + b.h;
    float d  = s - a.h;
    float e  = (a.h - (s - d)) + (b.h - d);
    e += a.l + b.l;
    float h = s + e;
    float l = (s - h) + e;
    return {h, l};
}
__device__ __forceinline__ ff ff_neg(ff a) { return {-a.h, -a.l}; }
// P*z for two two-floats
__device__ __forceinline__ ff ff_mul(ff a, ff z) {
    float p = a.h * z.h;
    float e = fmaf(a.h, z.h, -p);
    e = fmaf(a.h, z.l, e);
    e = fmaf(a.l, z.h, e);
    float h = p + e;
    float l = (p - h) + e;
    return {h, l};
}
// c + p where |c| >= |p| (fast two-sum)
__device__ __forceinline__ ff ff_cadd(float ch, float cl, ff p) {
    float s = ch + p.h;
    float e = (ch - s) + p.h;
    e += p.l + cl;
    float h = s + e;
    float l = (s - h) + e;
    return {h, l};
}
// exact scale by power of two / small exact ints
__device__ __forceinline__ ff ff_scale(ff a, float k) {   // k power of 2
    return {a.h * k, a.l * k};
}
__device__ __forceinline__ ff ff_mulf(ff a, float k) {    // general float k
    float p = k * a.h;
    float e = fmaf(k, a.h, -p);
    e = fmaf(k, a.l, e);
    float h = p + e;
    float l = (p - h) + e;
    return {h, l};
}

#define DFH(d) ((float)(d))
#define DFL(d) ((float)((d) - (double)(float)(d)))

// exp(z) for z = (zh,zl), |z| <= 0.3466, as two-float.  Taylor deg 11:
// tail c7..c11 in fp32 (weight <= 1.2e-7), df64 Horner c6..c0.
__device__ __forceinline__ ff ff_exp_core(float zh, float zl) {
    float t;
    t = fmaf(zh, 2.5052108385441718775e-8f, 2.7557319223985890653e-7f); // c11,c10
    t = fmaf(zh, t, 2.7557319223985890653e-6f);   // c9
    t = fmaf(zh, t, 2.4801587301587301588e-5f);   // c8
    t = fmaf(zh, t, 1.9841269841269841270e-4f);   // c7
    ff P = {t, 0.0f};
    ff z = {zh, zl};
    P = ff_cadd(DFH(1.0/720.0), DFL(1.0/720.0), ff_mul(P, z));
    P = ff_cadd(DFH(1.0/120.0), DFL(1.0/120.0), ff_mul(P, z));
    P = ff_cadd(DFH(1.0/24.0),  DFL(1.0/24.0),  ff_mul(P, z));
    P = ff_cadd(DFH(1.0/6.0),   DFL(1.0/6.0),   ff_mul(P, z));
    P = ff_cadd(0.5f, 0.0f, ff_mul(P, z));
    P = ff_cadd(1.0f, 0.0f, ff_mul(P, z));
    P = ff_cadd(1.0f, 0.0f, ff_mul(P, z));
    return P;
}

// sigmoid(y) correctly rounded to f32 (err ~1e-14 before the final rounding)
__device__ __forceinline__ float sigmoid_rn(float y) {
    float z = fminf(fmaxf(-y, -30.0f), 30.0f);
    float n = rintf(z * 1.4426950408889634f);
    // z - n*C1 exact: C1 has 9 mantissa bits, |n|<=44, result on common grid
    float rh = fmaf(-n, 0.693359375f, z);
    // remainder CR = ln2 - C1 (negative); r = rh - n*CR
    const double CRd = 0.69314718055994530942 - 0.693359375;
    ff p = ff_two_prod(-n, DFH(CRd));
    // two_sum(rh, p.h)
    float s  = rh + p.h;
    float d  = s - rh;
    float e  = (rh - (s - d)) + (p.h - d);
    e += p.l + (-n) * DFL(CRd);
    float z2h = s + e;
    float z2l = (s - z2h) + e;
    ff E = ff_exp_core(z2h, z2l);
    int ni = (int)n;
    float sc = __int_as_float((ni + 127) << 23);
    float th = E.h * sc, tl = E.l * sc;
    // s2 = 1 + t  (two_sum)
    float s2  = 1.0f + th;
    float d2  = s2 - 1.0f;
    float sl2 = (1.0f - (s2 - d2)) + (th - d2);
    sl2 += tl;
    // u = 1/s2 with one refined step (quadratic convergence from ~1e-7)
    float q0 = 1.0f / s2;
    float r  = fmaf(-q0, s2, 1.0f);
    r = fmaf(-q0, sl2, r);
    return fmaf(q0, r, q0);
}

// 2^e correctly rounded to f32 (e in ~(-6, 5))
__device__ __forceinline__ float exp2_rn(float e) {
    float n = rintf(e);
    float r = e - n;                     // exact, |r| <= 0.5
    const double LN2 = 0.69314718055994530942;
    float zh = r * DFH(LN2);
    float ze = fmaf(r, DFH(LN2), -zh);
    float zl = fmaf(r, DFL(LN2), ze);
    ff E = ff_exp_core(zh, zl);
    float pw = E.h + E.l;
    return pw * __int_as_float(((int)n + 127) << 23);
}

// ---------------------------------------------------------------------------
// Packed f32x2 helpers (FFMA2 — only reachable via PTX fma.rn.f32x2)
// ---------------------------------------------------------------------------
__device__ __forceinline__ unsigned long long pk2(float lo, float hi) {
    unsigned long long p;
    asm("mov.b64 %0, {%1, %2};" : "=l"(p) : "f"(lo), "f"(hi));
    return p;
}
__device__ __forceinline__ void upk2(unsigned long long p, float& lo, float& hi) {
    asm("mov.b64 {%0, %1}, %2;" : "=f"(lo), "=f"(hi) : "l"(p));
}
__device__ __forceinline__ unsigned long long fma2(unsigned long long a,
                                                   unsigned long long b,
                                                   unsigned long long c) {
    unsigned long long d;
    asm("fma.rn.f32x2 %0, %1, %2, %3;" : "=l"(d) : "l"(a), "l"(b), "l"(c));
    return d;
}

// ===========================================================================
// Fused prep: one block per (b,s).  Entirely fp32-pipe (df64), no fp64.
//
// jax.image.resize 'linear' (x256): coord(i) = (i+0.5)/256 - 0.5.
//   region 0   : samples [0,128)          constant f[0]
//   region r   : samples [256r-128,+256)  lerp f[r-1]->f[r], frac=(2i+1)/512
//   region 250 : samples [63872,64000)    constant f[249]
// phi(k) = P_base + k*om_prev + k^2*q,  k = 1..len, recentred at kc = len/2:
//   base' = P_base + kc*om_prev + kc^2*q  (mod 2pi),  w' = midpoint omega.
// ===========================================================================
__global__ void __launch_bounds__(256) prep_kernel(const float* __restrict__ amps_in,
                                                   const float* __restrict__ freqs_in) {
    __shared__ float2 s_om[TT];
    __shared__ float  s_a[TT];
    __shared__ float2 s_scan[256];

    int b = blockIdx.x / SS;
    int s = blockIdx.x % SS;
    int t = threadIdx.x;

    if (t < TT) {
        int gidx = (b*TT + t)*SS + s;

        // frequencies_sigmoid (depth=1) with f32 roundings matching reference
        float uf   = sigmoid_rn(freqs_in[gidx]);
        const float MIDI_MAX = 119.21309485364912f;   // np.float32(hz_to_midi(8000))
        float midi = uf * MIDI_MAX;
        float e    = (midi - 69.0f) / 12.0f;
        float pw   = exp2_rn(e);
        float freq = 440.0f * pw;

        // exp_sigmoid(amplitudes): fp32 fast path (amp enters linearly)
        float x  = amps_in[gidx];
        float sf = 1.0f / (1.0f + __expf(-x));
        float a  = 2.0f * __powf(sf, 2.3025850929940457f) + 1e-7f;
        if (freq >= 8000.0f) a = 0.0f;   // remove_above_nyquist

        const float CF = 3.9269908169872414e-4f;  // fp32(2*pi/16000)
        ff om = ff_two_prod(CF, freq);            // exact product
        s_om[t] = make_float2(om.h, om.l);
        s_a[t]  = a;
    }
    __syncthreads();

    // Segment increments: e_1 = 128*om_0; e_j = 128*(om_{j-2}+om_{j-1}).
    ff ev = {0.0f, 0.0f};
    if (t == 1) {
        ev = ff_scale({s_om[0].x, s_om[0].y}, 128.0f);
    } else if (t >= 2 && t <= 250) {
        ff a2 = ff_add({s_om[t-2].x, s_om[t-2].y}, {s_om[t-1].x, s_om[t-1].y});
        ev = ff_scale(a2, 128.0f);
    }
    s_scan[t] = make_float2(ev.h, ev.l);
    __syncthreads();

    // Inclusive Hillis-Steele scan (8 steps) in df64.
    #pragma unroll
    for (int off = 1; off < 256; off <<= 1) {
        float2 v2 = s_scan[t];
        ff v = {v2.x, v2.y};
        ff add = {0.0f, 0.0f};
        if (t >= off) { float2 a2 = s_scan[t - off]; add = {a2.x, a2.y}; }
        __syncthreads();
        ff r = ff_add(v, add);
        s_scan[t] = make_float2(r.h, r.l);
        __syncthreads();
    }

    if (t <= 250) {
        float2 P2 = s_scan[t];
        ff P = {P2.x, P2.y};
        ff base_df;
        float w, q, a0, da;
        if (t == 0) {
            ff om0 = {s_om[0].x, s_om[0].y};
            w = om0.h + om0.l; q = 0.0f;
            base_df = ff_scale(om0, 64.0f);
            a0 = s_a[0]; da = 0.0f;
        } else if (t == 250) {
            ff omN = {s_om[249].x, s_om[249].y};
            w = omN.h + omN.l; q = 0.0f;
            base_df = ff_add(P, ff_scale(omN, 64.0f));
            a0 = s_a[249]; da = 0.0f;
        } else {
            ff omp = {s_om[t-1].x, s_om[t-1].y};
            ff om  = {s_om[t].x,   s_om[t].y};
            ff qd  = ff_add(om, ff_neg(omp));
            q = (qd.h + qd.l) * (1.0f/512.0f);
            ff wv = ff_add(omp, om);
            w = 0.5f * (wv.h + wv.l);
            // base' = P + 96*om_prev + 32*om
            base_df = ff_add(P, ff_add(ff_mulf(omp, 96.0f), ff_scale(om, 32.0f)));
            a0 = s_a[t-1]; da = s_a[t] - s_a[t-1];
        }
        // reduce mod 2pi in df64
        const double T2P = 6.2831853071795864769;
        float nn = rintf(base_df.h * 0.15915494309189535f);
        ff m = ff_two_prod(nn, DFH(T2P));
        m.l = fmaf(nn, DFL(T2P), m.l);
        ff bred = ff_add(base_df, ff_neg(m));
        float base = bred.h + bred.l;

        int idx = (b*NREG + t)*SS + s;
        g_p4[idx] = make_float4(w, q, base, a0);
        g_da[idx] = da;
    }
}

// ---------------------------------------------------------------------------
// Synthesis: one block (128 threads) per region; 2 samples/thread, packed
// f32x2 FFMA2; params pre-duplicated in smem for LDS.128 packed operands.
// sin via MUFU __sinf on recentred phase (|t| <= ~500 rad).
// ---------------------------------------------------------------------------
__global__ void __launch_bounds__(128) synth_kernel(float* __restrict__ out) {
    __shared__ alignas(16) float sp[SS][12];  // [w,w][q,q][b,b][a0,a0][da,da][pad]

    int b   = blockIdx.x / NREG;
    int r   = blockIdx.x % NREG;
    int tid = threadIdx.x;

    if (tid < SS) {
        int idx = (b*NREG + r)*SS + tid;
        float4 v = g_p4[idx];
        float  d = g_da[idx];
        sp[tid][0] = v.x; sp[tid][1] = v.x;
        sp[tid][2] = v.y; sp[tid][3] = v.y;
        sp[tid][4] = v.z; sp[tid][5] = v.z;
        sp[tid][6] = v.w; sp[tid][7] = v.w;
        sp[tid][8] = d;   sp[tid][9] = d;
    }
    __syncthreads();

    int n0, half;
    if (r == 0)        { n0 = 0;         half = 64;  }
    else if (r == 250) { n0 = 63872;     half = 64;  }
    else               { n0 = 256*r-128; half = 128; }
    if (tid >= half) return;

    float k0 = (float)(tid + 1 - half);
    float k1 = (float)(tid + 1);
    unsigned long long kp  = pk2(k0, k1);
    unsigned long long fr2 = pk2((float)(2*tid + 1)          * (1.0f/512.0f),
                                 (float)(2*(tid + half) + 1) * (1.0f/512.0f));
    unsigned long long acc = 0ull;

    #pragma unroll
    for (int s = 0; s < SS; s++) {
        const unsigned long long* q8 = (const unsigned long long*)sp[s];
        unsigned long long ww = q8[0];
        unsigned long long qq = q8[1];
        unsigned long long bb = q8[2];
        unsigned long long aa = q8[3];
        unsigned long long dd = q8[4];

        unsigned long long h2 = fma2(kp, qq, ww);   // w' + k'q
        unsigned long long t2 = fma2(kp, h2, bb);   // base' + k'(w' + k'q)
        float t0, t1; upk2(t2, t0, t1);
        float s0 = __sinf(t0);
        float s1 = __sinf(t1);
        unsigned long long sv = pk2(s0, s1);
        unsigned long long am = fma2(fr2, dd, aa);  // a0 + fr*da
        acc = fma2(am, sv, acc);
    }

    float o0, o1; upk2(acc, o0, o1);
    out[(size_t)b*NSAMP + n0 + tid]        = o0;
    out[(size_t)b*NSAMP + n0 + tid + half] = o1;
}

// ---------------------------------------------------------------------------
extern "C" void kernel_launch(void* const* d_in, const int* in_sizes, int n_in,
                              void* d_out, int out_size) {
    const float* amplitudes  = (const float*)d_in[0];
    const float* frequencies = (const float*)d_in[1];
    float* out = (float*)d_out;
    (void)in_sizes; (void)n_in; (void)out_size;

    prep_kernel<<<BB*SS, 256>>>(amplitudes, frequencies);
    synth_kernel<<<BB*NREG, 128>>>(out);
}

// round 7
// speedup vs baseline: 13.2521x; 1.0935x over previous
#include <cuda_runtime.h>
#include <math.h>

// Problem dims
#define BB 8
#define TT 250
#define SS 64
#define NSAMP 64000
#define NREG 251          // head(128) + 249 full segments(256) + tail(128)

// Scratch (no cudaMalloc allowed)
__device__ float4 g_p4[BB*NREG*SS];   // {w' (midpoint omega), q, base' (mod 2pi), a0}
__device__ float  g_da[BB*NREG*SS];   // amp delta

// ===========================================================================
// double-single (two-float) arithmetic on the fp32 pipe (exact-FMA based).
// ===========================================================================
struct ff { float h, l; };

__device__ __forceinline__ ff ff_two_prod(float a, float b) {
    float p = a * b;
    float e = fmaf(a, b, -p);
    return {p, e};
}
__device__ __forceinline__ ff ff_add(ff a, ff b) {
    float s  = a.h + b.h;
    float d  = s - a.h;
    float e  = (a.h - (s - d)) + (b.h - d);
    e += a.l + b.l;
    float h = s + e;
    float l = (s - h) + e;
    return {h, l};
}
__device__ __forceinline__ ff ff_neg(ff a) { return {-a.h, -a.l}; }
__device__ __forceinline__ ff ff_mul(ff a, ff z) {
    float p = a.h * z.h;
    float e = fmaf(a.h, z.h, -p);
    e = fmaf(a.h, z.l, e);
    e = fmaf(a.l, z.h, e);
    float h = p + e;
    float l = (p - h) + e;
    return {h, l};
}
__device__ __forceinline__ ff ff_cadd(float ch, float cl, ff p) {
    float s = ch + p.h;
    float e = (ch - s) + p.h;
    e += p.l + cl;
    float h = s + e;
    float l = (s - h) + e;
    return {h, l};
}
__device__ __forceinline__ ff ff_scale(ff a, float k) {   // k power of 2
    return {a.h * k, a.l * k};
}
__device__ __forceinline__ ff ff_mulf(ff a, float k) {    // general float k
    float p = k * a.h;
    float e = fmaf(k, a.h, -p);
    e = fmaf(k, a.l, e);
    float h = p + e;
    float l = (p - h) + e;
    return {h, l};
}

#define DFH(d) ((float)(d))
#define DFL(d) ((float)((d) - (double)(float)(d)))

// exp(z), |z| <= 0.3466, as two-float.  Taylor deg 11 (tail fp32).
__device__ __forceinline__ ff ff_exp_core(float zh, float zl) {
    float t;
    t = fmaf(zh, 2.5052108385441718775e-8f, 2.7557319223985890653e-7f);
    t = fmaf(zh, t, 2.7557319223985890653e-6f);
    t = fmaf(zh, t, 2.4801587301587301588e-5f);
    t = fmaf(zh, t, 1.9841269841269841270e-4f);
    ff P = {t, 0.0f};
    ff z = {zh, zl};
    P = ff_cadd(DFH(1.0/720.0), DFL(1.0/720.0), ff_mul(P, z));
    P = ff_cadd(DFH(1.0/120.0), DFL(1.0/120.0), ff_mul(P, z));
    P = ff_cadd(DFH(1.0/24.0),  DFL(1.0/24.0),  ff_mul(P, z));
    P = ff_cadd(DFH(1.0/6.0),   DFL(1.0/6.0),   ff_mul(P, z));
    P = ff_cadd(0.5f, 0.0f, ff_mul(P, z));
    P = ff_cadd(1.0f, 0.0f, ff_mul(P, z));
    P = ff_cadd(1.0f, 0.0f, ff_mul(P, z));
    return P;
}

// sigmoid(y) correctly rounded to f32 (err ~1e-14 before final rounding)
__device__ __forceinline__ float sigmoid_rn(float y) {
    float z = fminf(fmaxf(-y, -30.0f), 30.0f);
    float n = rintf(z * 1.4426950408889634f);
    float rh = fmaf(-n, 0.693359375f, z);       // exact (9-bit constant)
    const double CRd = 0.69314718055994530942 - 0.693359375;
    ff p = ff_two_prod(-n, DFH(CRd));
    float s  = rh + p.h;
    float d  = s - rh;
    float e  = (rh - (s - d)) + (p.h - d);
    e += p.l + (-n) * DFL(CRd);
    float z2h = s + e;
    float z2l = (s - z2h) + e;
    ff E = ff_exp_core(z2h, z2l);
    int ni = (int)n;
    float sc = __int_as_float((ni + 127) << 23);
    float th = E.h * sc, tl = E.l * sc;
    float s2  = 1.0f + th;
    float d2  = s2 - 1.0f;
    float sl2 = (1.0f - (s2 - d2)) + (th - d2);
    sl2 += tl;
    float q0 = 1.0f / s2;
    float r  = fmaf(-q0, s2, 1.0f);
    r = fmaf(-q0, sl2, r);
    return fmaf(q0, r, q0);
}

// 2^e correctly rounded to f32 (e in ~(-6, 5))
__device__ __forceinline__ float exp2_rn(float e) {
    float n = rintf(e);
    float r = e - n;                     // exact
    const double LN2 = 0.69314718055994530942;
    float zh = r * DFH(LN2);
    float ze = fmaf(r, DFH(LN2), -zh);
    float zl = fmaf(r, DFL(LN2), ze);
    ff E = ff_exp_core(zh, zl);
    float pw = E.h + E.l;
    return pw * __int_as_float(((int)n + 127) << 23);
}

// ---------------------------------------------------------------------------
// Packed f32x2 helpers (FFMA2 — only reachable via PTX fma.rn.f32x2)
// ---------------------------------------------------------------------------
__device__ __forceinline__ unsigned long long pk2(float lo, float hi) {
    unsigned long long p;
    asm("mov.b64 %0, {%1, %2};" : "=l"(p) : "f"(lo), "f"(hi));
    return p;
}
__device__ __forceinline__ void upk2(unsigned long long p, float& lo, float& hi) {
    asm("mov.b64 {%0, %1}, %2;" : "=f"(lo), "=f"(hi) : "l"(p));
}
__device__ __forceinline__ unsigned long long fma2(unsigned long long a,
                                                   unsigned long long b,
                                                   unsigned long long c) {
    unsigned long long d;
    asm("fma.rn.f32x2 %0, %1, %2, %3;" : "=l"(d) : "l"(a), "l"(b), "l"(c));
    return d;
}

// ===========================================================================
// Fused prep: one block (256 thr) per (b,s).  All fp32-pipe (df64), no fp64.
// Scan done with warp shuffles (2 barriers instead of 16).
//
// jax.image.resize 'linear' (x256): coord(i) = (i+0.5)/256 - 0.5.
//   region 0   : samples [0,128)          constant f[0]
//   region r   : samples [256r-128,+256)  lerp f[r-1]->f[r], frac=(2i+1)/512
//   region 250 : samples [63872,64000)    constant f[249]
// phi(k) = P_base + k*om_prev + k^2*q, recentred at kc = len/2.
// ===========================================================================
__global__ void __launch_bounds__(256) prep_kernel(const float* __restrict__ amps_in,
                                                   const float* __restrict__ freqs_in) {
    __shared__ float2 s_om[TT];
    __shared__ float  s_a[TT];
    __shared__ float2 s_wsum[8];

    int b = blockIdx.x / SS;
    int s = blockIdx.x % SS;
    int t = threadIdx.x;
    int lane = t & 31, warp = t >> 5;

    if (t < TT) {
        int gidx = (b*TT + t)*SS + s;

        float uf   = sigmoid_rn(freqs_in[gidx]);
        const float MIDI_MAX = 119.21309485364912f;   // np.float32(hz_to_midi(8000))
        float midi = uf * MIDI_MAX;
        float e    = (midi - 69.0f) / 12.0f;
        float pw   = exp2_rn(e);
        float freq = 440.0f * pw;

        float x  = amps_in[gidx];
        float sf = 1.0f / (1.0f + __expf(-x));
        float a  = 2.0f * __powf(sf, 2.3025850929940457f) + 1e-7f;
        if (freq >= 8000.0f) a = 0.0f;   // remove_above_nyquist

        const float CF = 3.9269908169872414e-4f;  // fp32(2*pi/16000)
        ff om = ff_two_prod(CF, freq);            // exact product
        s_om[t] = make_float2(om.h, om.l);
        s_a[t]  = a;
    }
    __syncthreads();

    // Segment increments: e_1 = 128*om_0; e_j = 128*(om_{j-2}+om_{j-1}).
    ff v = {0.0f, 0.0f};
    if (t == 1) {
        v = ff_scale({s_om[0].x, s_om[0].y}, 128.0f);
    } else if (t >= 2 && t <= 250) {
        ff a2 = ff_add({s_om[t-2].x, s_om[t-2].y}, {s_om[t-1].x, s_om[t-1].y});
        v = ff_scale(a2, 128.0f);
    }

    // Warp-level inclusive df64 scan (5 shfl steps).
    #pragma unroll
    for (int d = 1; d < 32; d <<= 1) {
        float oh = __shfl_up_sync(0xffffffffu, v.h, d);
        float ol = __shfl_up_sync(0xffffffffu, v.l, d);
        if (lane >= d) v = ff_add(v, {oh, ol});
    }
    if (lane == 31) s_wsum[warp] = make_float2(v.h, v.l);
    __syncthreads();
    // Add prefix of earlier warps' sums (<=7 df64 adds per thread).
    #pragma unroll
    for (int wprev = 0; wprev < 7; wprev++) {
        if (wprev < warp) {
            float2 ws = s_wsum[wprev];
            v = ff_add(v, {ws.x, ws.y});
        }
    }
    ff P = v;   // inclusive prefix: P_base of region t

    if (t <= 250) {
        ff base_df;
        float w, q, a0, da;
        if (t == 0) {
            ff om0 = {s_om[0].x, s_om[0].y};
            w = om0.h + om0.l; q = 0.0f;
            base_df = ff_scale(om0, 64.0f);
            a0 = s_a[0]; da = 0.0f;
        } else if (t == 250) {
            ff omN = {s_om[249].x, s_om[249].y};
            w = omN.h + omN.l; q = 0.0f;
            base_df = ff_add(P, ff_scale(omN, 64.0f));
            a0 = s_a[249]; da = 0.0f;
        } else {
            ff omp = {s_om[t-1].x, s_om[t-1].y};
            ff om  = {s_om[t].x,   s_om[t].y};
            ff qd  = ff_add(om, ff_neg(omp));
            q = (qd.h + qd.l) * (1.0f/512.0f);
            ff wv = ff_add(omp, om);
            w = 0.5f * (wv.h + wv.l);
            base_df = ff_add(P, ff_add(ff_mulf(omp, 96.0f), ff_scale(om, 32.0f)));
            a0 = s_a[t-1]; da = s_a[t] - s_a[t-1];
        }
        const double T2P = 6.2831853071795864769;
        float nn = rintf(base_df.h * 0.15915494309189535f);
        ff m = ff_two_prod(nn, DFH(T2P));
        m.l = fmaf(nn, DFL(T2P), m.l);
        ff bred = ff_add(base_df, ff_neg(m));
        float base = bred.h + bred.l;

        int idx = (b*NREG + t)*SS + s;
        g_p4[idx] = make_float4(w, q, base, a0);
        g_da[idx] = da;
    }
}

// ---------------------------------------------------------------------------
// Synthesis: one 64-thread block per region; 4 samples/thread, two packed
// f32x2 accumulators.  Param smem traffic amortized over 4 samples.
// Pair A = positions (tid, tid+half);  Pair B = (tid+64, tid+64+half).
// Edge regions (half=64) only store pair A.
// ---------------------------------------------------------------------------
__global__ void __launch_bounds__(64) synth_kernel(float* __restrict__ out) {
    __shared__ alignas(16) float sp[SS][12];  // [w,w][q,q][b,b][a0,a0][da,da][pad]

    int b   = blockIdx.x / NREG;
    int r   = blockIdx.x % NREG;
    int tid = threadIdx.x;

    {
        int idx = (b*NREG + r)*SS + tid;
        float4 v = g_p4[idx];
        float  d = g_da[idx];
        sp[tid][0] = v.x; sp[tid][1] = v.x;
        sp[tid][2] = v.y; sp[tid][3] = v.y;
        sp[tid][4] = v.z; sp[tid][5] = v.z;
        sp[tid][6] = v.w; sp[tid][7] = v.w;
        sp[tid][8] = d;   sp[tid][9] = d;
    }
    __syncthreads();

    int n0, half;
    if (r == 0)        { n0 = 0;         half = 64;  }
    else if (r == 250) { n0 = 63872;     half = 64;  }
    else               { n0 = 256*r-128; half = 128; }
    bool full = (half == 128);

    // k' = (pos+1) - half  (recentred at segment midpoint)
    float kA0 = (float)(tid + 1 - half);
    float kA1 = (float)(tid + 1);
    float kB0 = (float)(tid + 65 - half);
    float kB1 = (float)(tid + 65);
    unsigned long long kpA = pk2(kA0, kA1);
    unsigned long long kpB = pk2(kB0, kB1);
    unsigned long long frA = pk2((float)(2*tid + 1)            * (1.0f/512.0f),
                                 (float)(2*(tid + half) + 1)   * (1.0f/512.0f));
    unsigned long long frB = pk2((float)(2*(tid+64) + 1)        * (1.0f/512.0f),
                                 (float)(2*(tid+64+half) + 1)   * (1.0f/512.0f));
    unsigned long long accA = 0ull, accB = 0ull;

    #pragma unroll
    for (int s = 0; s < SS; s++) {
        const unsigned long long* q8 = (const unsigned long long*)sp[s];
        unsigned long long ww = q8[0];
        unsigned long long qq = q8[1];
        unsigned long long bb = q8[2];
        unsigned long long aa = q8[3];
        unsigned long long dd = q8[4];

        unsigned long long hA = fma2(kpA, qq, ww);
        unsigned long long tA = fma2(kpA, hA, bb);
        unsigned long long hB = fma2(kpB, qq, ww);
        unsigned long long tB = fma2(kpB, hB, bb);
        float tA0, tA1, tB0, tB1;
        upk2(tA, tA0, tA1);
        upk2(tB, tB0, tB1);
        float sA0 = __sinf(tA0);
        float sA1 = __sinf(tA1);
        float sB0 = __sinf(tB0);
        float sB1 = __sinf(tB1);
        unsigned long long svA = pk2(sA0, sA1);
        unsigned long long svB = pk2(sB0, sB1);
        unsigned long long amA = fma2(frA, dd, aa);
        unsigned long long amB = fma2(frB, dd, aa);
        accA = fma2(amA, svA, accA);
        accB = fma2(amB, svB, accB);
    }

    float oA0, oA1, oB0, oB1;
    upk2(accA, oA0, oA1);
    upk2(accB, oB0, oB1);
    float* ob = out + (size_t)b*NSAMP + n0;
    ob[tid]        = oA0;
    ob[tid + half] = oA1;
    if (full) {
        ob[tid + 64]        = oB0;
        ob[tid + 64 + half] = oB1;
    }
}

// ---------------------------------------------------------------------------
extern "C" void kernel_launch(void* const* d_in, const int* in_sizes, int n_in,
                              void* d_out, int out_size) {
    const float* amplitudes  = (const float*)d_in[0];
    const float* frequencies = (const float*)d_in[1];
    float* out = (float*)d_out;
    (void)in_sizes; (void)n_in; (void)out_size;

    prep_kernel<<<BB*SS, 256>>>(amplitudes, frequencies);
    synth_kernel<<<BB*NREG, 64>>>(out);
}

// round 8
// speedup vs baseline: 13.4088x; 1.0118x over previous
#include <cuda_runtime.h>
#include <math.h>

// Problem dims
#define BB 8
#define TT 250
#define SS 64
#define NSAMP 64000
#define NREG 251          // head(128) + 249 full segments(256) + tail(128)

// Scratch (no cudaMalloc allowed)
__device__ float4 g_p4[BB*NREG*SS];   // {w' (midpoint omega), q, base' (mod 2pi), a0}
__device__ float  g_da[BB*NREG*SS];   // amp delta

// ===========================================================================
// double-single (two-float) arithmetic on the fp32 pipe (exact-FMA based).
// ===========================================================================
struct ff { float h, l; };

__device__ __forceinline__ ff ff_two_prod(float a, float b) {
    float p = a * b;
    float e = fmaf(a, b, -p);
    return {p, e};
}
__device__ __forceinline__ ff ff_add(ff a, ff b) {
    float s  = a.h + b.h;
    float d  = s - a.h;
    float e  = (a.h - (s - d)) + (b.h - d);
    e += a.l + b.l;
    float h = s + e;
    float l = (s - h) + e;
    return {h, l};
}
__device__ __forceinline__ ff ff_neg(ff a) { return {-a.h, -a.l}; }
__device__ __forceinline__ ff ff_mul(ff a, ff z) {
    float p = a.h * z.h;
    float e = fmaf(a.h, z.h, -p);
    e = fmaf(a.h, z.l, e);
    e = fmaf(a.l, z.h, e);
    float h = p + e;
    float l = (p - h) + e;
    return {h, l};
}
__device__ __forceinline__ ff ff_cadd(float ch, float cl, ff p) {
    float s = ch + p.h;
    float e = (ch - s) + p.h;
    e += p.l + cl;
    float h = s + e;
    float l = (s - h) + e;
    return {h, l};
}
__device__ __forceinline__ ff ff_scale(ff a, float k) {   // k power of 2
    return {a.h * k, a.l * k};
}
__device__ __forceinline__ ff ff_mulf(ff a, float k) {    // general float k
    float p = k * a.h;
    float e = fmaf(k, a.h, -p);
    e = fmaf(k, a.l, e);
    float h = p + e;
    float l = (p - h) + e;
    return {h, l};
}

#define DFH(d) ((float)(d))
#define DFL(d) ((float)((d) - (double)(float)(d)))

// exp(z), |z| <= 0.3466, as two-float.  Taylor deg 11 (tail fp32).
__device__ __forceinline__ ff ff_exp_core(float zh, float zl) {
    float t;
    t = fmaf(zh, 2.5052108385441718775e-8f, 2.7557319223985890653e-7f);
    t = fmaf(zh, t, 2.7557319223985890653e-6f);
    t = fmaf(zh, t, 2.4801587301587301588e-5f);
    t = fmaf(zh, t, 1.9841269841269841270e-4f);
    ff P = {t, 0.0f};
    ff z = {zh, zl};
    P = ff_cadd(DFH(1.0/720.0), DFL(1.0/720.0), ff_mul(P, z));
    P = ff_cadd(DFH(1.0/120.0), DFL(1.0/120.0), ff_mul(P, z));
    P = ff_cadd(DFH(1.0/24.0),  DFL(1.0/24.0),  ff_mul(P, z));
    P = ff_cadd(DFH(1.0/6.0),   DFL(1.0/6.0),   ff_mul(P, z));
    P = ff_cadd(0.5f, 0.0f, ff_mul(P, z));
    P = ff_cadd(1.0f, 0.0f, ff_mul(P, z));
    P = ff_cadd(1.0f, 0.0f, ff_mul(P, z));
    return P;
}

// sigmoid(y) correctly rounded to f32 (err ~1e-14 before final rounding)
__device__ __forceinline__ float sigmoid_rn(float y) {
    float z = fminf(fmaxf(-y, -30.0f), 30.0f);
    float n = rintf(z * 1.4426950408889634f);
    float rh = fmaf(-n, 0.693359375f, z);       // exact (9-bit constant)
    const double CRd = 0.69314718055994530942 - 0.693359375;
    ff p = ff_two_prod(-n, DFH(CRd));
    float s  = rh + p.h;
    float d  = s - rh;
    float e  = (rh - (s - d)) + (p.h - d);
    e += p.l + (-n) * DFL(CRd);
    float z2h = s + e;
    float z2l = (s - z2h) + e;
    ff E = ff_exp_core(z2h, z2l);
    int ni = (int)n;
    float sc = __int_as_float((ni + 127) << 23);
    float th = E.h * sc, tl = E.l * sc;
    float s2  = 1.0f + th;
    float d2  = s2 - 1.0f;
    float sl2 = (1.0f - (s2 - d2)) + (th - d2);
    sl2 += tl;
    float q0 = 1.0f / s2;
    float r  = fmaf(-q0, s2, 1.0f);
    r = fmaf(-q0, sl2, r);
    return fmaf(q0, r, q0);
}

// 2^e correctly rounded to f32 (e in ~(-6, 5))
__device__ __forceinline__ float exp2_rn(float e) {
    float n = rintf(e);
    float r = e - n;                     // exact
    const double LN2 = 0.69314718055994530942;
    float zh = r * DFH(LN2);
    float ze = fmaf(r, DFH(LN2), -zh);
    float zl = fmaf(r, DFL(LN2), ze);
    ff E = ff_exp_core(zh, zl);
    float pw = E.h + E.l;
    return pw * __int_as_float(((int)n + 127) << 23);
}

// ---------------------------------------------------------------------------
// Packed f32x2 helpers (FFMA2 — only reachable via PTX fma.rn.f32x2)
// ---------------------------------------------------------------------------
__device__ __forceinline__ unsigned long long pk2(float lo, float hi) {
    unsigned long long p;
    asm("mov.b64 %0, {%1, %2};" : "=l"(p) : "f"(lo), "f"(hi));
    return p;
}
__device__ __forceinline__ void upk2(unsigned long long p, float& lo, float& hi) {
    asm("mov.b64 {%0, %1}, %2;" : "=f"(lo), "=f"(hi) : "l"(p));
}
__device__ __forceinline__ unsigned long long fma2(unsigned long long a,
                                                   unsigned long long b,
                                                   unsigned long long c) {
    unsigned long long d;
    asm("fma.rn.f32x2 %0, %1, %2, %3;" : "=l"(d) : "l"(a), "l"(b), "l"(c));
    return d;
}
__device__ __forceinline__ unsigned long long add2(unsigned long long a,
                                                   unsigned long long b) {
    unsigned long long d;
    asm("add.rn.f32x2 %0, %1, %2;" : "=l"(d) : "l"(a), "l"(b));
    return d;
}

// ===========================================================================
// Fused prep: one block (256 thr) per (b,s).  All fp32-pipe (df64), no fp64.
//
// jax.image.resize 'linear' (x256): coord(i) = (i+0.5)/256 - 0.5.
//   region 0   : samples [0,128)          constant f[0]
//   region r   : samples [256r-128,+256)  lerp f[r-1]->f[r], frac=(2i+1)/512
//   region 250 : samples [63872,64000)    constant f[249]
// phi(k) = P_base + k*om_prev + k^2*q, recentred at kc = len/2.
// ===========================================================================
__global__ void __launch_bounds__(256) prep_kernel(const float* __restrict__ amps_in,
                                                   const float* __restrict__ freqs_in) {
    __shared__ float2 s_om[TT];
    __shared__ float  s_a[TT];
    __shared__ float2 s_wsum[8];

    int b = blockIdx.x / SS;
    int s = blockIdx.x % SS;
    int t = threadIdx.x;
    int lane = t & 31, warp = t >> 5;

    if (t < TT) {
        int gidx = (b*TT + t)*SS + s;

        float uf   = sigmoid_rn(freqs_in[gidx]);
        const float MIDI_MAX = 119.21309485364912f;   // np.float32(hz_to_midi(8000))
        float midi = uf * MIDI_MAX;
        float e    = (midi - 69.0f) / 12.0f;
        float pw   = exp2_rn(e);
        float freq = 440.0f * pw;

        float x  = amps_in[gidx];
        float sf = 1.0f / (1.0f + __expf(-x));
        float a  = 2.0f * __powf(sf, 2.3025850929940457f) + 1e-7f;
        if (freq >= 8000.0f) a = 0.0f;   // remove_above_nyquist

        const float CF = 3.9269908169872414e-4f;  // fp32(2*pi/16000)
        ff om = ff_two_prod(CF, freq);            // exact product
        s_om[t] = make_float2(om.h, om.l);
        s_a[t]  = a;
    }
    __syncthreads();

    // Segment increments: e_1 = 128*om_0; e_j = 128*(om_{j-2}+om_{j-1}).
    ff v = {0.0f, 0.0f};
    if (t == 1) {
        v = ff_scale({s_om[0].x, s_om[0].y}, 128.0f);
    } else if (t >= 2 && t <= 250) {
        ff a2 = ff_add({s_om[t-2].x, s_om[t-2].y}, {s_om[t-1].x, s_om[t-1].y});
        v = ff_scale(a2, 128.0f);
    }

    // Warp-level inclusive df64 scan (5 shfl steps).
    #pragma unroll
    for (int d = 1; d < 32; d <<= 1) {
        float oh = __shfl_up_sync(0xffffffffu, v.h, d);
        float ol = __shfl_up_sync(0xffffffffu, v.l, d);
        if (lane >= d) v = ff_add(v, {oh, ol});
    }
    if (lane == 31) s_wsum[warp] = make_float2(v.h, v.l);
    __syncthreads();
    #pragma unroll
    for (int wprev = 0; wprev < 7; wprev++) {
        if (wprev < warp) {
            float2 ws = s_wsum[wprev];
            v = ff_add(v, {ws.x, ws.y});
        }
    }
    ff P = v;   // inclusive prefix: P_base of region t

    if (t <= 250) {
        ff base_df;
        float w, q, a0, da;
        if (t == 0) {
            ff om0 = {s_om[0].x, s_om[0].y};
            w = om0.h + om0.l; q = 0.0f;
            base_df = ff_scale(om0, 64.0f);
            a0 = s_a[0]; da = 0.0f;
        } else if (t == 250) {
            ff omN = {s_om[249].x, s_om[249].y};
            w = omN.h + omN.l; q = 0.0f;
            base_df = ff_add(P, ff_scale(omN, 64.0f));
            a0 = s_a[249]; da = 0.0f;
        } else {
            ff omp = {s_om[t-1].x, s_om[t-1].y};
            ff om  = {s_om[t].x,   s_om[t].y};
            ff qd  = ff_add(om, ff_neg(omp));
            q = (qd.h + qd.l) * (1.0f/512.0f);
            ff wv = ff_add(omp, om);
            w = 0.5f * (wv.h + wv.l);
            base_df = ff_add(P, ff_add(ff_mulf(omp, 96.0f), ff_scale(om, 32.0f)));
            a0 = s_a[t-1]; da = s_a[t] - s_a[t-1];
        }
        const double T2P = 6.2831853071795864769;
        float nn = rintf(base_df.h * 0.15915494309189535f);
        ff m = ff_two_prod(nn, DFH(T2P));
        m.l = fmaf(nn, DFL(T2P), m.l);
        ff bred = ff_add(base_df, ff_neg(m));
        float base = bred.h + bred.l;

        int idx = (b*NREG + t)*SS + s;
        g_p4[idx] = make_float4(w, q, base, a0);
        g_da[idx] = da;
    }
}

// ---------------------------------------------------------------------------
// Synthesis: one 128-thread block per region.  Harmonics split across the
// two 64-thread halves (hw=0: harmonics 0..31, hw=1: 32..63) to double
// concurrent warps (occupancy) while keeping 4 samples/thread (low issue
// count per sample).  Partial sums combined through smem.
// Pair A = positions (ts, ts+half);  Pair B = (ts+64, ts+64+half).
// ---------------------------------------------------------------------------
__global__ void __launch_bounds__(128) synth_kernel(float* __restrict__ out) {
    __shared__ alignas(16) float sp[SS][12];  // [w,w][q,q][b,b][a0,a0][da,da][pad]
    __shared__ alignas(16) unsigned long long redA[64], redB[64];

    int b   = blockIdx.x / NREG;
    int r   = blockIdx.x % NREG;
    int tid = threadIdx.x;
    int ts  = tid & 63;          // sample group
    int hw  = tid >> 6;          // harmonic half (0 or 1)

    if (tid < SS) {
        int idx = (b*NREG + r)*SS + tid;
        float4 v = g_p4[idx];
        float  d = g_da[idx];
        sp[tid][0] = v.x; sp[tid][1] = v.x;
        sp[tid][2] = v.y; sp[tid][3] = v.y;
        sp[tid][4] = v.z; sp[tid][5] = v.z;
        sp[tid][6] = v.w; sp[tid][7] = v.w;
        sp[tid][8] = d;   sp[tid][9] = d;
    }
    __syncthreads();

    int n0, half;
    if (r == 0)        { n0 = 0;         half = 64;  }
    else if (r == 250) { n0 = 63872;     half = 64;  }
    else               { n0 = 256*r-128; half = 128; }
    bool full = (half == 128);

    // k' = (pos+1) - half  (recentred at segment midpoint)
    float kA0 = (float)(ts + 1 - half);
    float kA1 = (float)(ts + 1);
    float kB0 = (float)(ts + 65 - half);
    float kB1 = (float)(ts + 65);
    unsigned long long kpA = pk2(kA0, kA1);
    unsigned long long kpB = pk2(kB0, kB1);
    unsigned long long frA = pk2((float)(2*ts + 1)            * (1.0f/512.0f),
                                 (float)(2*(ts + half) + 1)   * (1.0f/512.0f));
    unsigned long long frB = pk2((float)(2*(ts+64) + 1)        * (1.0f/512.0f),
                                 (float)(2*(ts+64+half) + 1)   * (1.0f/512.0f));
    unsigned long long accA = 0ull, accB = 0ull;

    int sbeg = hw << 5;   // 0 or 32
    #pragma unroll
    for (int si = 0; si < 32; si++) {
        const unsigned long long* q8 = (const unsigned long long*)sp[sbeg + si];
        unsigned long long ww = q8[0];
        unsigned long long qq = q8[1];
        unsigned long long bb = q8[2];
        unsigned long long aa = q8[3];
        unsigned long long dd = q8[4];

        unsigned long long hA = fma2(kpA, qq, ww);
        unsigned long long tA = fma2(kpA, hA, bb);
        unsigned long long hB = fma2(kpB, qq, ww);
        unsigned long long tB = fma2(kpB, hB, bb);
        float tA0, tA1, tB0, tB1;
        upk2(tA, tA0, tA1);
        upk2(tB, tB0, tB1);
        float sA0 = __sinf(tA0);
        float sA1 = __sinf(tA1);
        float sB0 = __sinf(tB0);
        float sB1 = __sinf(tB1);
        unsigned long long svA = pk2(sA0, sA1);
        unsigned long long svB = pk2(sB0, sB1);
        unsigned long long amA = fma2(frA, dd, aa);
        unsigned long long amB = fma2(frB, dd, aa);
        accA = fma2(amA, svA, accA);
        accB = fma2(amB, svB, accB);
    }

    // Combine the two harmonic halves.
    if (hw == 1) {
        redA[ts] = accA;
        redB[ts] = accB;
    }
    __syncthreads();
    if (hw == 0) {
        accA = add2(accA, redA[ts]);
        accB = add2(accB, redB[ts]);
        float oA0, oA1, oB0, oB1;
        upk2(accA, oA0, oA1);
        upk2(accB, oB0, oB1);
        float* ob = out + (size_t)b*NSAMP + n0;
        ob[ts]        = oA0;
        ob[ts + half] = oA1;
        if (full) {
            ob[ts + 64]        = oB0;
            ob[ts + 64 + half] = oB1;
        }
    }
}

// ---------------------------------------------------------------------------
extern "C" void kernel_launch(void* const* d_in, const int* in_sizes, int n_in,
                              void* d_out, int out_size) {
    const float* amplitudes  = (const float*)d_in[0];
    const float* frequencies = (const float*)d_in[1];
    float* out = (float*)d_out;
    (void)in_sizes; (void)n_in; (void)out_size;

    prep_kernel<<<BB*SS, 256>>>(amplitudes, frequencies);
    synth_kernel<<<BB*NREG, 128>>>(out);
}